// round 13
// baseline (speedup 1.0000x reference)
#include <cuda_runtime.h>
#include <cuda_fp16.h>
#include <cstdint>

#define D_MODEL 1024
#define LSEQ    2048
#define NB      2
#define NHEAD   16
#define HD      64
#define NTOK    (NB * LSEQ)   // 4096

// Scratch (device globals — alloc-free per harness rules)
__device__ __half g_qkv[(size_t)NTOK * 3 * D_MODEL];      // [4096, 3072] fp16
__device__ __half g_xh[(size_t)NTOK * D_MODEL];           // x, fp16
__device__ __half g_wqkvh[(size_t)D_MODEL * 3 * D_MODEL]; // W_qkv, fp16
__device__ __half g_wouth[(size_t)D_MODEL * D_MODEL];     // W_out, fp16
__device__ __half g_attnh[(size_t)NTOK * D_MODEL];        // attn out, fp16

// ---------------------------------------------------------------------------
// helpers
// ---------------------------------------------------------------------------
__device__ __forceinline__ void mma_f16(float c[4], const uint32_t a[4], const uint32_t b[2]) {
    asm volatile(
        "mma.sync.aligned.m16n8k16.row.col.f32.f16.f16.f32 "
        "{%0,%1,%2,%3}, {%4,%5,%6,%7}, {%8,%9}, {%0,%1,%2,%3};"
        : "+f"(c[0]), "+f"(c[1]), "+f"(c[2]), "+f"(c[3])
        : "r"(a[0]), "r"(a[1]), "r"(a[2]), "r"(a[3]),
          "r"(b[0]), "r"(b[1]));
}

__device__ __forceinline__ uint32_t pack_half2(float lo, float hi) {
    uint32_t r;
    asm("cvt.rn.f16x2.f32 %0, %1, %2;" : "=r"(r) : "f"(hi), "f"(lo));
    return r;
}

__device__ __forceinline__ uint32_t smem_u32(const void* p) {
    return (uint32_t)__cvta_generic_to_shared(p);
}

__device__ __forceinline__ void ldmatrix_x4(uint32_t& r0, uint32_t& r1,
                                            uint32_t& r2, uint32_t& r3, uint32_t addr) {
    asm volatile("ldmatrix.sync.aligned.m8n8.x4.shared.b16 {%0,%1,%2,%3}, [%4];"
                 : "=r"(r0), "=r"(r1), "=r"(r2), "=r"(r3) : "r"(addr));
}
__device__ __forceinline__ void ldmatrix_x4_trans(uint32_t& r0, uint32_t& r1,
                                                  uint32_t& r2, uint32_t& r3, uint32_t addr) {
    asm volatile("ldmatrix.sync.aligned.m8n8.x4.trans.shared.b16 {%0,%1,%2,%3}, [%4];"
                 : "=r"(r0), "=r"(r1), "=r"(r2), "=r"(r3) : "r"(addr));
}

__device__ __forceinline__ void cp_async16(void* smem_dst, const void* gmem_src) {
    uint32_t dst = smem_u32(smem_dst);
    asm volatile("cp.async.cg.shared.global [%0], [%1], 16;" :: "r"(dst), "l"(gmem_src));
}
__device__ __forceinline__ void cp_async_commit() {
    asm volatile("cp.async.commit_group;");
}
template <int N>
__device__ __forceinline__ void cp_async_wait() {
    asm volatile("cp.async.wait_group %0;" :: "n"(N));
}

// ---------------------------------------------------------------------------
// Prep: fp32 -> fp16 (RN)
// ---------------------------------------------------------------------------
__global__ void to_f16_kernel(const float* __restrict__ src,
                              __half* __restrict__ dst, int n4) {
    int i = blockIdx.x * blockDim.x + threadIdx.x;
    if (i < n4) {
        float4 v = reinterpret_cast<const float4*>(src)[i];
        __half2 h0 = __floats2half2_rn(v.x, v.y);
        __half2 h1 = __floats2half2_rn(v.z, v.w);
        reinterpret_cast<__half2*>(dst)[2 * i]     = h0;
        reinterpret_cast<__half2*>(dst)[2 * i + 1] = h1;
    }
}

// ---------------------------------------------------------------------------
// fp16 tensor-core GEMM (m16n8k16), 4-stage cp.async, ONE sync per k-iter.
// Unchanged from R11 (validated, 89us QKV).
// ---------------------------------------------------------------------------
#define STAGES 4
#define A_STG  (128 * 40)
#define B_STG  (32 * 136)
#define GEMM_SMEM ((STAGES * (A_STG + B_STG)) * 2)

template <bool HALF_OUT>
__global__ __launch_bounds__(256, 2)
void gemm_f16_kernel(const __half* __restrict__ A,
                     const __half* __restrict__ B,
                     const float* __restrict__ bias,
                     void* __restrict__ Cv,
                     int M, int N, int K) {
    extern __shared__ __align__(16) __half smh[];
    __half* As = smh;                    // [STAGES][128][40]
    __half* Bs = smh + STAGES * A_STG;   // [STAGES][32][136]

    const int tid  = threadIdx.x;
    const int w    = tid >> 5;
    const int lane = tid & 31;
    const int gid  = lane >> 2;
    const int tig  = lane & 3;
    const int wm   = w >> 2;
    const int wn   = w & 3;

    const int rowBase = blockIdx.y * 128;
    const int colBase = blockIdx.x * 128;

    const int a_r0 = tid >> 2,          a_c0 = (tid & 3) << 3;
    const int a_r1 = (tid + 256) >> 2,  a_c1 = ((tid + 256) & 3) << 3;
    const int b_r0 = tid >> 4,          b_c0 = (tid & 15) << 3;
    const int b_r1 = (tid + 256) >> 4,  b_c1 = ((tid + 256) & 15) << 3;

    const int lrow = lane & 15;
    const int lhi  = (lane >> 4) << 3;

    float acc[4][4][4];
    #pragma unroll
    for (int mt = 0; mt < 4; mt++)
        #pragma unroll
        for (int nt = 0; nt < 4; nt++)
            #pragma unroll
            for (int r = 0; r < 4; r++) acc[mt][nt][r] = 0.0f;

    const int KITERS = K >> 5;

    #pragma unroll
    for (int s = 0; s < STAGES - 1; s++) {
        const int k0 = s << 5;
        cp_async16(&As[s * A_STG + a_r0 * 40 + a_c0], &A[(size_t)(rowBase + a_r0) * K + k0 + a_c0]);
        cp_async16(&As[s * A_STG + a_r1 * 40 + a_c1], &A[(size_t)(rowBase + a_r1) * K + k0 + a_c1]);
        cp_async16(&Bs[s * B_STG + b_r0 * 136 + b_c0], &B[(size_t)(k0 + b_r0) * N + colBase + b_c0]);
        cp_async16(&Bs[s * B_STG + b_r1 * 136 + b_c1], &B[(size_t)(k0 + b_r1) * N + colBase + b_c1]);
        cp_async_commit();
    }

    for (int iter = 0; iter < KITERS; iter++) {
        const int buf = iter % STAGES;
        cp_async_wait<STAGES - 2>();
        __syncthreads();

        const __half* Ab = As + buf * A_STG;
        const __half* Bb = Bs + buf * B_STG;

        #pragma unroll
        for (int kc = 0; kc < 2; kc++) {
            const int kb = kc << 4;
            uint32_t afr[4][4], bfr[4][2];
            #pragma unroll
            for (int mt = 0; mt < 4; mt++) {
                uint32_t addr = smem_u32(&Ab[(wm * 64 + mt * 16 + lrow) * 40 + kb + lhi]);
                ldmatrix_x4(afr[mt][0], afr[mt][1], afr[mt][2], afr[mt][3], addr);
            }
            #pragma unroll
            for (int ntp = 0; ntp < 2; ntp++) {
                uint32_t addr = smem_u32(&Bb[(kb + lrow) * 136 + wn * 32 + ntp * 16 + lhi]);
                uint32_t r0, r1, r2, r3;
                ldmatrix_x4_trans(r0, r1, r2, r3, addr);
                bfr[2 * ntp][0] = r0;      bfr[2 * ntp][1] = r1;
                bfr[2 * ntp + 1][0] = r2;  bfr[2 * ntp + 1][1] = r3;
            }
            #pragma unroll
            for (int mt = 0; mt < 4; mt++)
                #pragma unroll
                for (int nt = 0; nt < 4; nt++)
                    mma_f16(acc[mt][nt], afr[mt], bfr[nt]);
        }

        const int kload = iter + STAGES - 1;
        if (kload < KITERS) {
            const int sbuf = kload % STAGES;
            const int k0 = kload << 5;
            cp_async16(&As[sbuf * A_STG + a_r0 * 40 + a_c0], &A[(size_t)(rowBase + a_r0) * K + k0 + a_c0]);
            cp_async16(&As[sbuf * A_STG + a_r1 * 40 + a_c1], &A[(size_t)(rowBase + a_r1) * K + k0 + a_c1]);
            cp_async16(&Bs[sbuf * B_STG + b_r0 * 136 + b_c0], &B[(size_t)(k0 + b_r0) * N + colBase + b_c0]);
            cp_async16(&Bs[sbuf * B_STG + b_r1 * 136 + b_c1], &B[(size_t)(k0 + b_r1) * N + colBase + b_c1]);
        }
        cp_async_commit();
    }

    #pragma unroll
    for (int mt = 0; mt < 4; mt++) {
        int r0 = rowBase + wm * 64 + mt * 16 + gid;
        #pragma unroll
        for (int nt = 0; nt < 4; nt++) {
            int c0 = colBase + wn * 32 + nt * 8 + 2 * tig;
            float bi0 = bias[c0], bi1 = bias[c0 + 1];
            float s00 = acc[mt][nt][0] + bi0, s01 = acc[mt][nt][1] + bi1;
            float s10 = acc[mt][nt][2] + bi0, s11 = acc[mt][nt][3] + bi1;
            if (HALF_OUT) {
                __half* Ch = (__half*)Cv;
                *reinterpret_cast<uint32_t*>(&Ch[(size_t)r0       * N + c0]) = pack_half2(s00, s01);
                *reinterpret_cast<uint32_t*>(&Ch[(size_t)(r0 + 8) * N + c0]) = pack_half2(s10, s11);
            } else {
                float* Cf = (float*)Cv;
                *reinterpret_cast<float2*>(&Cf[(size_t)r0       * N + c0]) = make_float2(s00, s01);
                *reinterpret_cast<float2*>(&Cf[(size_t)(r0 + 8) * N + c0]) = make_float2(s10, s11);
            }
        }
    }
}

// ---------------------------------------------------------------------------
// fp16 tensor-core flash attention (causal), Q tile = 128 rows.
// 256 threads = 8 warps, warp = 16 Q rows; KV tiles of 64, double-buffered
// cp.async. KV tile-loads per CTA halve vs the 64-row version; warps/SM
// 12 -> 16. Fully-masked warp slabs skip their compute block (no barriers
// inside the guard). Per-Q-row MMA sequence identical -> bit-identical
// numerics expected.
// ---------------------------------------------------------------------------
#define KV_STRIDE 72
#define KV_TILE_H (64 * KV_STRIDE)
#define ATTN_SMEM (4 * KV_TILE_H * 2)   // 36864 B

__global__ __launch_bounds__(256, 2)
void attn_f16_kernel() {
    extern __shared__ __align__(16) __half smh[];
    __half* KsB = smh;                    // [2][64][72]
    __half* VsB = smh + 2 * KV_TILE_H;    // [2][64][72]

    const int qt = gridDim.x - 1 - blockIdx.x;   // heavy CTAs first
    const int h  = blockIdx.y;
    const int b  = blockIdx.z;

    const int tid  = threadIdx.x;
    const int warp = tid >> 5;          // 0..7
    const int lane = tid & 31;
    const int gid  = lane >> 2;
    const int tig  = lane & 3;
    const int lrow = lane & 15;
    const int lhi  = (lane >> 4) << 3;
    const int wrow = warp * 16;         // 0..112
    const int qrow0 = qt * 128;
    const int grow0 = qrow0 + wrow;     // warp's first global Q row
    const float scale = 0.125f;

    // Q fragments (m16n8k16 A layout)
    uint32_t qf[4][4];
    {
        const __half* Qb = g_qkv + (size_t)(b * LSEQ + grow0) * 3072 + h * 64;
        #pragma unroll
        for (int kc = 0; kc < 4; kc++) {
            qf[kc][0] = *reinterpret_cast<const uint32_t*>(&Qb[(size_t)gid       * 3072 + kc * 16 + 2 * tig    ]);
            qf[kc][1] = *reinterpret_cast<const uint32_t*>(&Qb[(size_t)(gid + 8) * 3072 + kc * 16 + 2 * tig    ]);
            qf[kc][2] = *reinterpret_cast<const uint32_t*>(&Qb[(size_t)gid       * 3072 + kc * 16 + 2 * tig + 8]);
            qf[kc][3] = *reinterpret_cast<const uint32_t*>(&Qb[(size_t)(gid + 8) * 3072 + kc * 16 + 2 * tig + 8]);
        }
    }

    float o[8][4];
    #pragma unroll
    for (int nt = 0; nt < 8; nt++)
        #pragma unroll
        for (int j = 0; j < 4; j++) o[nt][j] = 0.0f;
    float m0 = -1e30f, m8 = -1e30f, l0 = 0.0f, l8 = 0.0f;

    // Tile loader: 64x64 fp16 K and V = 512 16B-chunks each; 2+2 per thread
    auto load_tile = [&](int kt, int buf) {
        const __half* base = g_qkv + (size_t)(b * LSEQ + kt * 64) * 3072 + h * 64;
        __half* kd = KsB + buf * KV_TILE_H;
        __half* vd = VsB + buf * KV_TILE_H;
        #pragma unroll
        for (int c = tid; c < 512; c += 256) {
            int r = c >> 3, c8 = (c & 7) << 3;
            const __half* src = base + (size_t)r * 3072 + c8;
            cp_async16(kd + r * KV_STRIDE + c8, src + 1024);
            cp_async16(vd + r * KV_STRIDE + c8, src + 2048);
        }
    };

    const int nkt = 2 * qt + 2;   // KV tiles covering [0, qrow0+128)

    load_tile(0, 0);
    cp_async_commit();

    for (int kt = 0; kt < nkt; kt++) {
        const int buf = kt & 1;
        const int kv0 = kt * 64;
        cp_async_wait<0>();
        __syncthreads();

        if (kt + 1 < nkt) load_tile(kt + 1, buf ^ 1);
        cp_async_commit();

        // Skip fully-masked warp slabs (keys all strictly above diagonal)
        if (kv0 > grow0 + 15) continue;   // no barriers below

        const __half* Kb = KsB + buf * KV_TILE_H;
        const __half* Vb = VsB + buf * KV_TILE_H;

        // S = Q @ K^T
        float s[8][4];
        #pragma unroll
        for (int nt = 0; nt < 8; nt++)
            #pragma unroll
            for (int j = 0; j < 4; j++) s[nt][j] = 0.0f;

        #pragma unroll
        for (int kc = 0; kc < 4; kc++) {
            #pragma unroll
            for (int ntp = 0; ntp < 4; ntp++) {
                uint32_t addr = smem_u32(&Kb[(ntp * 16 + lrow) * KV_STRIDE + kc * 16 + lhi]);
                uint32_t r0, r1, r2, r3;
                ldmatrix_x4(r0, r1, r2, r3, addr);
                uint32_t b0[2] = {r0, r2};
                uint32_t b1[2] = {r1, r3};
                mma_f16(s[2 * ntp],     qf[kc], b0);
                mma_f16(s[2 * ntp + 1], qf[kc], b1);
            }
        }

        #pragma unroll
        for (int nt = 0; nt < 8; nt++)
            #pragma unroll
            for (int j = 0; j < 4; j++) s[nt][j] *= scale;

        // Causal mask (only tiles crossing this warp's diagonal band)
        if (kv0 + 63 > grow0) {
            const int r0 = grow0 + gid, r8 = r0 + 8;
            #pragma unroll
            for (int nt = 0; nt < 8; nt++) {
                int c = kv0 + nt * 8 + 2 * tig;
                if (c     > r0) s[nt][0] = -1e30f;
                if (c + 1 > r0) s[nt][1] = -1e30f;
                if (c     > r8) s[nt][2] = -1e30f;
                if (c + 1 > r8) s[nt][3] = -1e30f;
            }
        }

        // Online softmax
        float mt0 = -1e30f, mt8 = -1e30f;
        #pragma unroll
        for (int nt = 0; nt < 8; nt++) {
            mt0 = fmaxf(mt0, fmaxf(s[nt][0], s[nt][1]));
            mt8 = fmaxf(mt8, fmaxf(s[nt][2], s[nt][3]));
        }
        #pragma unroll
        for (int off = 1; off < 4; off <<= 1) {
            mt0 = fmaxf(mt0, __shfl_xor_sync(0xffffffffu, mt0, off));
            mt8 = fmaxf(mt8, __shfl_xor_sync(0xffffffffu, mt8, off));
        }
        const float mn0 = fmaxf(m0, mt0), mn8 = fmaxf(m8, mt8);
        const float a0 = __expf(m0 - mn0), a8 = __expf(m8 - mn8);

        float rs0 = 0.0f, rs8 = 0.0f;
        #pragma unroll
        for (int nt = 0; nt < 8; nt++) {
            s[nt][0] = __expf(s[nt][0] - mn0);
            s[nt][1] = __expf(s[nt][1] - mn0);
            s[nt][2] = __expf(s[nt][2] - mn8);
            s[nt][3] = __expf(s[nt][3] - mn8);
            rs0 += s[nt][0] + s[nt][1];
            rs8 += s[nt][2] + s[nt][3];
            o[nt][0] *= a0; o[nt][1] *= a0;
            o[nt][2] *= a8; o[nt][3] *= a8;
        }
        #pragma unroll
        for (int off = 1; off < 4; off <<= 1) {
            rs0 += __shfl_xor_sync(0xffffffffu, rs0, off);
            rs8 += __shfl_xor_sync(0xffffffffu, rs8, off);
        }
        l0 = l0 * a0 + rs0;
        l8 = l8 * a8 + rs8;
        m0 = mn0; m8 = mn8;

        // O += P @ V : S C-fragment packs directly into fp16 A-fragment
        #pragma unroll
        for (int kc2 = 0; kc2 < 4; kc2++) {
            uint32_t af[4];
            af[0] = pack_half2(s[2 * kc2    ][0], s[2 * kc2    ][1]);
            af[1] = pack_half2(s[2 * kc2    ][2], s[2 * kc2    ][3]);
            af[2] = pack_half2(s[2 * kc2 + 1][0], s[2 * kc2 + 1][1]);
            af[3] = pack_half2(s[2 * kc2 + 1][2], s[2 * kc2 + 1][3]);
            #pragma unroll
            for (int ntp = 0; ntp < 4; ntp++) {
                uint32_t addr = smem_u32(&Vb[(kc2 * 16 + lrow) * KV_STRIDE + ntp * 16 + lhi]);
                uint32_t r0, r1, r2, r3;
                ldmatrix_x4_trans(r0, r1, r2, r3, addr);
                uint32_t b0[2] = {r0, r1};
                uint32_t b1[2] = {r2, r3};
                mma_f16(o[2 * ntp],     af, b0);
                mma_f16(o[2 * ntp + 1], af, b1);
            }
        }
    }

    // Epilogue: normalize, store fp16 for out-proj
    const float inv0 = 1.0f / l0, inv8 = 1.0f / l8;
    __half* dsth = g_attnh + (size_t)(b * LSEQ + grow0) * D_MODEL + h * 64;
    #pragma unroll
    for (int nt = 0; nt < 8; nt++) {
        int c = nt * 8 + 2 * tig;
        *reinterpret_cast<uint32_t*>(dsth + (size_t)gid       * D_MODEL + c) =
            pack_half2(o[nt][0] * inv0, o[nt][1] * inv0);
        *reinterpret_cast<uint32_t*>(dsth + (size_t)(gid + 8) * D_MODEL + c) =
            pack_half2(o[nt][2] * inv8, o[nt][3] * inv8);
    }
}

// ---------------------------------------------------------------------------
extern "C" void kernel_launch(void* const* d_in, const int* in_sizes, int n_in,
                              void* d_out, int out_size) {
    const float* x     = (const float*)d_in[0];
    const float* W_qkv = (const float*)d_in[1];
    const float* b_qkv = (const float*)d_in[2];
    const float* W_out = (const float*)d_in[3];
    const float* b_out = (const float*)d_in[4];
    float* out = (float*)d_out;

    __half* qkv;   cudaGetSymbolAddress((void**)&qkv,   g_qkv);
    __half* xh;    cudaGetSymbolAddress((void**)&xh,    g_xh);
    __half* wqkvh; cudaGetSymbolAddress((void**)&wqkvh, g_wqkvh);
    __half* wouth; cudaGetSymbolAddress((void**)&wouth, g_wouth);
    __half* attnh; cudaGetSymbolAddress((void**)&attnh, g_attnh);

    cudaFuncSetAttribute(attn_f16_kernel,
                         cudaFuncAttributeMaxDynamicSharedMemorySize, ATTN_SMEM);
    cudaFuncSetAttribute(gemm_f16_kernel<true>,
                         cudaFuncAttributeMaxDynamicSharedMemorySize, GEMM_SMEM);
    cudaFuncSetAttribute(gemm_f16_kernel<false>,
                         cudaFuncAttributeMaxDynamicSharedMemorySize, GEMM_SMEM);

    // 0) Convert inputs to fp16
    {
        int n4x = NTOK * D_MODEL / 4;
        int n4q = D_MODEL * 3 * D_MODEL / 4;
        int n4o = D_MODEL * D_MODEL / 4;
        to_f16_kernel<<<(n4x + 255) / 256, 256>>>(x, xh, n4x);
        to_f16_kernel<<<(n4q + 255) / 256, 256>>>(W_qkv, wqkvh, n4q);
        to_f16_kernel<<<(n4o + 255) / 256, 256>>>(W_out, wouth, n4o);
    }

    // 1) QKV projection (fp16 TC, fp16 output)
    dim3 g1(3 * D_MODEL / 128, NTOK / 128);
    gemm_f16_kernel<true><<<g1, 256, GEMM_SMEM>>>(xh, wqkvh, b_qkv, qkv, NTOK, 3 * D_MODEL, D_MODEL);

    // 2) Causal flash attention (fp16 TC, Q tile 128)
    dim3 g2(LSEQ / 128, NHEAD, NB);
    attn_f16_kernel<<<g2, 256, ATTN_SMEM>>>();

    // 3) Output projection (fp16 TC, fp32 output)
    dim3 g3(D_MODEL / 128, NTOK / 128);
    gemm_f16_kernel<false><<<g3, 256, GEMM_SMEM>>>(attnh, wouth, b_out, out, NTOK, D_MODEL, D_MODEL);
}

// round 14
// speedup vs baseline: 1.0539x; 1.0539x over previous
#include <cuda_runtime.h>
#include <cuda_fp16.h>
#include <cstdint>

#define D_MODEL 1024
#define LSEQ    2048
#define NB      2
#define NHEAD   16
#define HD      64
#define NTOK    (NB * LSEQ)   // 4096

// Scratch (device globals — alloc-free per harness rules)
__device__ __half g_qkv[(size_t)NTOK * 3 * D_MODEL];      // [4096, 3072] fp16
__device__ __half g_xh[(size_t)NTOK * D_MODEL];           // x, fp16
__device__ __half g_wqkvh[(size_t)D_MODEL * 3 * D_MODEL]; // W_qkv, fp16
__device__ __half g_wouth[(size_t)D_MODEL * D_MODEL];     // W_out, fp16
__device__ __half g_attnh[(size_t)NTOK * D_MODEL];        // attn out, fp16

// ---------------------------------------------------------------------------
// helpers
// ---------------------------------------------------------------------------
__device__ __forceinline__ void mma_f16(float c[4], const uint32_t a[4], const uint32_t b[2]) {
    asm volatile(
        "mma.sync.aligned.m16n8k16.row.col.f32.f16.f16.f32 "
        "{%0,%1,%2,%3}, {%4,%5,%6,%7}, {%8,%9}, {%0,%1,%2,%3};"
        : "+f"(c[0]), "+f"(c[1]), "+f"(c[2]), "+f"(c[3])
        : "r"(a[0]), "r"(a[1]), "r"(a[2]), "r"(a[3]),
          "r"(b[0]), "r"(b[1]));
}

__device__ __forceinline__ uint32_t pack_half2(float lo, float hi) {
    uint32_t r;
    asm("cvt.rn.f16x2.f32 %0, %1, %2;" : "=r"(r) : "f"(hi), "f"(lo));
    return r;
}

__device__ __forceinline__ uint32_t smem_u32(const void* p) {
    return (uint32_t)__cvta_generic_to_shared(p);
}

__device__ __forceinline__ void ldmatrix_x4(uint32_t& r0, uint32_t& r1,
                                            uint32_t& r2, uint32_t& r3, uint32_t addr) {
    asm volatile("ldmatrix.sync.aligned.m8n8.x4.shared.b16 {%0,%1,%2,%3}, [%4];"
                 : "=r"(r0), "=r"(r1), "=r"(r2), "=r"(r3) : "r"(addr));
}
__device__ __forceinline__ void ldmatrix_x4_trans(uint32_t& r0, uint32_t& r1,
                                                  uint32_t& r2, uint32_t& r3, uint32_t addr) {
    asm volatile("ldmatrix.sync.aligned.m8n8.x4.trans.shared.b16 {%0,%1,%2,%3}, [%4];"
                 : "=r"(r0), "=r"(r1), "=r"(r2), "=r"(r3) : "r"(addr));
}

__device__ __forceinline__ void cp_async16(void* smem_dst, const void* gmem_src) {
    uint32_t dst = smem_u32(smem_dst);
    asm volatile("cp.async.cg.shared.global [%0], [%1], 16;" :: "r"(dst), "l"(gmem_src));
}
__device__ __forceinline__ void cp_async_commit() {
    asm volatile("cp.async.commit_group;");
}
template <int N>
__device__ __forceinline__ void cp_async_wait() {
    asm volatile("cp.async.wait_group %0;" :: "n"(N));
}

// ---------------------------------------------------------------------------
// Prep: fp32 -> fp16 (RN)
// ---------------------------------------------------------------------------
__global__ void to_f16_kernel(const float* __restrict__ src,
                              __half* __restrict__ dst, int n4) {
    int i = blockIdx.x * blockDim.x + threadIdx.x;
    if (i < n4) {
        float4 v = reinterpret_cast<const float4*>(src)[i];
        __half2 h0 = __floats2half2_rn(v.x, v.y);
        __half2 h1 = __floats2half2_rn(v.z, v.w);
        reinterpret_cast<__half2*>(dst)[2 * i]     = h0;
        reinterpret_cast<__half2*>(dst)[2 * i + 1] = h1;
    }
}

// ---------------------------------------------------------------------------
// fp16 tensor-core GEMM (m16n8k16), BK=64, 3-stage cp.async, ONE sync per
// k-iter (16 iters -> 16 barriers vs 32 before). Same single-sync invariant
// as R11: refill target (iter+2)%3 was last read at iter-1; top sync covers.
// Dynamic smem: 3*(128*72 + 64*136)*2 = 107520 B -> 2 CTAs/SM.
// ---------------------------------------------------------------------------
#define STAGES 3
#define A_STRIDE 72
#define B_STRIDE 136
#define A_STG  (128 * A_STRIDE)
#define B_STG  (64 * B_STRIDE)
#define GEMM_SMEM ((STAGES * (A_STG + B_STG)) * 2)

template <bool HALF_OUT>
__global__ __launch_bounds__(256, 2)
void gemm_f16_kernel(const __half* __restrict__ A,
                     const __half* __restrict__ B,
                     const float* __restrict__ bias,
                     void* __restrict__ Cv,
                     int M, int N, int K) {
    extern __shared__ __align__(16) __half smh[];
    __half* As = smh;                    // [STAGES][128][72]
    __half* Bs = smh + STAGES * A_STG;   // [STAGES][64][136]

    const int tid  = threadIdx.x;
    const int w    = tid >> 5;
    const int lane = tid & 31;
    const int gid  = lane >> 2;
    const int tig  = lane & 3;
    const int wm   = w >> 2;
    const int wn   = w & 3;

    const int rowBase = blockIdx.y * 128;
    const int colBase = blockIdx.x * 128;

    const int lrow = lane & 15;
    const int lhi  = (lane >> 4) << 3;

    float acc[4][4][4];
    #pragma unroll
    for (int mt = 0; mt < 4; mt++)
        #pragma unroll
        for (int nt = 0; nt < 4; nt++)
            #pragma unroll
            for (int r = 0; r < 4; r++) acc[mt][nt][r] = 0.0f;

    const int KITERS = K >> 6;   // BK=64

    // Loader: A tile 128x64 halves = 1024 16B-chunks; B tile 64x128 = 1024.
    // 4 + 4 chunks per thread.
    auto load_slab = [&](int kblk, int sbuf) {
        const int k0 = kblk << 6;
        __half* ad = As + sbuf * A_STG;
        __half* bd = Bs + sbuf * B_STG;
        #pragma unroll
        for (int c = tid; c < 1024; c += 256) {
            int ar = c >> 3, ac = (c & 7) << 3;        // A: row 0..127, col8
            cp_async16(ad + ar * A_STRIDE + ac, &A[(size_t)(rowBase + ar) * K + k0 + ac]);
            int br = c >> 4, bc = (c & 15) << 3;       // B: row 0..63, col8
            cp_async16(bd + br * B_STRIDE + bc, &B[(size_t)(k0 + br) * N + colBase + bc]);
        }
    };

    #pragma unroll
    for (int s = 0; s < STAGES - 1; s++) {
        load_slab(s, s);
        cp_async_commit();
    }

    for (int iter = 0; iter < KITERS; iter++) {
        const int buf = iter % STAGES;
        cp_async_wait<STAGES - 2>();
        __syncthreads();    // the ONLY barrier per iter

        const __half* Ab = As + buf * A_STG;
        const __half* Bb = Bs + buf * B_STG;

        #pragma unroll
        for (int kc = 0; kc < 4; kc++) {
            const int kb = kc << 4;
            uint32_t afr[4][4], bfr[4][2];
            #pragma unroll
            for (int mt = 0; mt < 4; mt++) {
                uint32_t addr = smem_u32(&Ab[(wm * 64 + mt * 16 + lrow) * A_STRIDE + kb + lhi]);
                ldmatrix_x4(afr[mt][0], afr[mt][1], afr[mt][2], afr[mt][3], addr);
            }
            #pragma unroll
            for (int ntp = 0; ntp < 2; ntp++) {
                uint32_t addr = smem_u32(&Bb[(kb + lrow) * B_STRIDE + wn * 32 + ntp * 16 + lhi]);
                uint32_t r0, r1, r2, r3;
                ldmatrix_x4_trans(r0, r1, r2, r3, addr);
                bfr[2 * ntp][0] = r0;      bfr[2 * ntp][1] = r1;
                bfr[2 * ntp + 1][0] = r2;  bfr[2 * ntp + 1][1] = r3;
            }
            #pragma unroll
            for (int mt = 0; mt < 4; mt++)
                #pragma unroll
                for (int nt = 0; nt < 4; nt++)
                    mma_f16(acc[mt][nt], afr[mt], bfr[nt]);
        }

        const int kload = iter + STAGES - 1;
        if (kload < KITERS) load_slab(kload, kload % STAGES);
        cp_async_commit();
    }

    #pragma unroll
    for (int mt = 0; mt < 4; mt++) {
        int r0 = rowBase + wm * 64 + mt * 16 + gid;
        #pragma unroll
        for (int nt = 0; nt < 4; nt++) {
            int c0 = colBase + wn * 32 + nt * 8 + 2 * tig;
            float bi0 = bias[c0], bi1 = bias[c0 + 1];
            float s00 = acc[mt][nt][0] + bi0, s01 = acc[mt][nt][1] + bi1;
            float s10 = acc[mt][nt][2] + bi0, s11 = acc[mt][nt][3] + bi1;
            if (HALF_OUT) {
                __half* Ch = (__half*)Cv;
                *reinterpret_cast<uint32_t*>(&Ch[(size_t)r0       * N + c0]) = pack_half2(s00, s01);
                *reinterpret_cast<uint32_t*>(&Ch[(size_t)(r0 + 8) * N + c0]) = pack_half2(s10, s11);
            } else {
                float* Cf = (float*)Cv;
                *reinterpret_cast<float2*>(&Cf[(size_t)r0       * N + c0]) = make_float2(s00, s01);
                *reinterpret_cast<float2*>(&Cf[(size_t)(r0 + 8) * N + c0]) = make_float2(s10, s11);
            }
        }
    }
}

// ---------------------------------------------------------------------------
// fp16 tensor-core flash attention (causal) — R11 structure (64-row Q,
// 128 threads, 1024 CTAs: best measured balance), now 4 CTAs/SM.
// ---------------------------------------------------------------------------
#define KV_STRIDE 72
#define KV_TILE_H (64 * KV_STRIDE)
#define ATTN_SMEM (4 * KV_TILE_H * 2)

__global__ __launch_bounds__(128, 4)
void attn_f16_kernel() {
    extern __shared__ __align__(16) __half smh[];
    __half* KsB = smh;                    // [2][64][72]
    __half* VsB = smh + 2 * KV_TILE_H;    // [2][64][72]

    const int qt = gridDim.x - 1 - blockIdx.x;   // heavy CTAs first
    const int h  = blockIdx.y;
    const int b  = blockIdx.z;

    const int tid  = threadIdx.x;
    const int warp = tid >> 5;
    const int lane = tid & 31;
    const int gid  = lane >> 2;
    const int tig  = lane & 3;
    const int lrow = lane & 15;
    const int lhi  = (lane >> 4) << 3;
    const int wrow = warp * 16;
    const int qrow0 = qt * 64;
    const float scale = 0.125f;

    uint32_t qf[4][4];
    {
        const __half* Qb = g_qkv + (size_t)(b * LSEQ + qrow0 + wrow) * 3072 + h * 64;
        #pragma unroll
        for (int kc = 0; kc < 4; kc++) {
            qf[kc][0] = *reinterpret_cast<const uint32_t*>(&Qb[(size_t)gid       * 3072 + kc * 16 + 2 * tig    ]);
            qf[kc][1] = *reinterpret_cast<const uint32_t*>(&Qb[(size_t)(gid + 8) * 3072 + kc * 16 + 2 * tig    ]);
            qf[kc][2] = *reinterpret_cast<const uint32_t*>(&Qb[(size_t)gid       * 3072 + kc * 16 + 2 * tig + 8]);
            qf[kc][3] = *reinterpret_cast<const uint32_t*>(&Qb[(size_t)(gid + 8) * 3072 + kc * 16 + 2 * tig + 8]);
        }
    }

    float o[8][4];
    #pragma unroll
    for (int nt = 0; nt < 8; nt++)
        #pragma unroll
        for (int j = 0; j < 4; j++) o[nt][j] = 0.0f;
    float m0 = -1e30f, m8 = -1e30f, l0 = 0.0f, l8 = 0.0f;

    auto load_tile = [&](int kt, int buf) {
        const __half* base = g_qkv + (size_t)(b * LSEQ + kt * 64) * 3072 + h * 64;
        __half* kd = KsB + buf * KV_TILE_H;
        __half* vd = VsB + buf * KV_TILE_H;
        #pragma unroll
        for (int c = tid; c < 512; c += 128) {
            int r = c >> 3, c8 = (c & 7) << 3;
            const __half* src = base + (size_t)r * 3072 + c8;
            cp_async16(kd + r * KV_STRIDE + c8, src + 1024);
            cp_async16(vd + r * KV_STRIDE + c8, src + 2048);
        }
    };

    load_tile(0, 0);
    cp_async_commit();

    for (int kt = 0; kt <= qt; kt++) {
        const int buf = kt & 1;
        cp_async_wait<0>();
        __syncthreads();

        if (kt < qt) load_tile(kt + 1, buf ^ 1);
        cp_async_commit();

        const __half* Kb = KsB + buf * KV_TILE_H;
        const __half* Vb = VsB + buf * KV_TILE_H;

        float s[8][4];
        #pragma unroll
        for (int nt = 0; nt < 8; nt++)
            #pragma unroll
            for (int j = 0; j < 4; j++) s[nt][j] = 0.0f;

        #pragma unroll
        for (int kc = 0; kc < 4; kc++) {
            #pragma unroll
            for (int ntp = 0; ntp < 4; ntp++) {
                uint32_t addr = smem_u32(&Kb[(ntp * 16 + lrow) * KV_STRIDE + kc * 16 + lhi]);
                uint32_t r0, r1, r2, r3;
                ldmatrix_x4(r0, r1, r2, r3, addr);
                uint32_t b0[2] = {r0, r2};
                uint32_t b1[2] = {r1, r3};
                mma_f16(s[2 * ntp],     qf[kc], b0);
                mma_f16(s[2 * ntp + 1], qf[kc], b1);
            }
        }

        #pragma unroll
        for (int nt = 0; nt < 8; nt++)
            #pragma unroll
            for (int j = 0; j < 4; j++) s[nt][j] *= scale;

        if (kt == qt) {
            const int r0 = wrow + gid, r8 = r0 + 8;
            #pragma unroll
            for (int nt = 0; nt < 8; nt++) {
                int c = nt * 8 + 2 * tig;
                if (c     > r0) s[nt][0] = -1e30f;
                if (c + 1 > r0) s[nt][1] = -1e30f;
                if (c     > r8) s[nt][2] = -1e30f;
                if (c + 1 > r8) s[nt][3] = -1e30f;
            }
        }

        float mt0 = -1e30f, mt8 = -1e30f;
        #pragma unroll
        for (int nt = 0; nt < 8; nt++) {
            mt0 = fmaxf(mt0, fmaxf(s[nt][0], s[nt][1]));
            mt8 = fmaxf(mt8, fmaxf(s[nt][2], s[nt][3]));
        }
        #pragma unroll
        for (int off = 1; off < 4; off <<= 1) {
            mt0 = fmaxf(mt0, __shfl_xor_sync(0xffffffffu, mt0, off));
            mt8 = fmaxf(mt8, __shfl_xor_sync(0xffffffffu, mt8, off));
        }
        const float mn0 = fmaxf(m0, mt0), mn8 = fmaxf(m8, mt8);
        const float a0 = __expf(m0 - mn0), a8 = __expf(m8 - mn8);

        float rs0 = 0.0f, rs8 = 0.0f;
        #pragma unroll
        for (int nt = 0; nt < 8; nt++) {
            s[nt][0] = __expf(s[nt][0] - mn0);
            s[nt][1] = __expf(s[nt][1] - mn0);
            s[nt][2] = __expf(s[nt][2] - mn8);
            s[nt][3] = __expf(s[nt][3] - mn8);
            rs0 += s[nt][0] + s[nt][1];
            rs8 += s[nt][2] + s[nt][3];
            o[nt][0] *= a0; o[nt][1] *= a0;
            o[nt][2] *= a8; o[nt][3] *= a8;
        }
        #pragma unroll
        for (int off = 1; off < 4; off <<= 1) {
            rs0 += __shfl_xor_sync(0xffffffffu, rs0, off);
            rs8 += __shfl_xor_sync(0xffffffffu, rs8, off);
        }
        l0 = l0 * a0 + rs0;
        l8 = l8 * a8 + rs8;
        m0 = mn0; m8 = mn8;

        #pragma unroll
        for (int kc2 = 0; kc2 < 4; kc2++) {
            uint32_t af[4];
            af[0] = pack_half2(s[2 * kc2    ][0], s[2 * kc2    ][1]);
            af[1] = pack_half2(s[2 * kc2    ][2], s[2 * kc2    ][3]);
            af[2] = pack_half2(s[2 * kc2 + 1][0], s[2 * kc2 + 1][1]);
            af[3] = pack_half2(s[2 * kc2 + 1][2], s[2 * kc2 + 1][3]);
            #pragma unroll
            for (int ntp = 0; ntp < 4; ntp++) {
                uint32_t addr = smem_u32(&Vb[(kc2 * 16 + lrow) * KV_STRIDE + ntp * 16 + lhi]);
                uint32_t r0, r1, r2, r3;
                ldmatrix_x4_trans(r0, r1, r2, r3, addr);
                uint32_t b0[2] = {r0, r1};
                uint32_t b1[2] = {r2, r3};
                mma_f16(o[2 * ntp],     af, b0);
                mma_f16(o[2 * ntp + 1], af, b1);
            }
        }
    }

    const float inv0 = 1.0f / l0, inv8 = 1.0f / l8;
    __half* dsth = g_attnh + (size_t)(b * LSEQ + qrow0 + wrow) * D_MODEL + h * 64;
    #pragma unroll
    for (int nt = 0; nt < 8; nt++) {
        int c = nt * 8 + 2 * tig;
        *reinterpret_cast<uint32_t*>(dsth + (size_t)gid       * D_MODEL + c) =
            pack_half2(o[nt][0] * inv0, o[nt][1] * inv0);
        *reinterpret_cast<uint32_t*>(dsth + (size_t)(gid + 8) * D_MODEL + c) =
            pack_half2(o[nt][2] * inv8, o[nt][3] * inv8);
    }
}

// ---------------------------------------------------------------------------
extern "C" void kernel_launch(void* const* d_in, const int* in_sizes, int n_in,
                              void* d_out, int out_size) {
    const float* x     = (const float*)d_in[0];
    const float* W_qkv = (const float*)d_in[1];
    const float* b_qkv = (const float*)d_in[2];
    const float* W_out = (const float*)d_in[3];
    const float* b_out = (const float*)d_in[4];
    float* out = (float*)d_out;

    __half* qkv;   cudaGetSymbolAddress((void**)&qkv,   g_qkv);
    __half* xh;    cudaGetSymbolAddress((void**)&xh,    g_xh);
    __half* wqkvh; cudaGetSymbolAddress((void**)&wqkvh, g_wqkvh);
    __half* wouth; cudaGetSymbolAddress((void**)&wouth, g_wouth);
    __half* attnh; cudaGetSymbolAddress((void**)&attnh, g_attnh);

    cudaFuncSetAttribute(attn_f16_kernel,
                         cudaFuncAttributeMaxDynamicSharedMemorySize, ATTN_SMEM);
    cudaFuncSetAttribute(gemm_f16_kernel<true>,
                         cudaFuncAttributeMaxDynamicSharedMemorySize, GEMM_SMEM);
    cudaFuncSetAttribute(gemm_f16_kernel<false>,
                         cudaFuncAttributeMaxDynamicSharedMemorySize, GEMM_SMEM);

    // 0) Convert inputs to fp16
    {
        int n4x = NTOK * D_MODEL / 4;
        int n4q = D_MODEL * 3 * D_MODEL / 4;
        int n4o = D_MODEL * D_MODEL / 4;
        to_f16_kernel<<<(n4x + 255) / 256, 256>>>(x, xh, n4x);
        to_f16_kernel<<<(n4q + 255) / 256, 256>>>(W_qkv, wqkvh, n4q);
        to_f16_kernel<<<(n4o + 255) / 256, 256>>>(W_out, wouth, n4o);
    }

    // 1) QKV projection (fp16 TC, fp16 output)
    dim3 g1(3 * D_MODEL / 128, NTOK / 128);
    gemm_f16_kernel<true><<<g1, 256, GEMM_SMEM>>>(xh, wqkvh, b_qkv, qkv, NTOK, 3 * D_MODEL, D_MODEL);

    // 2) Causal flash attention (fp16 TC, 64-row Q tiles)
    dim3 g2(LSEQ / 64, NHEAD, NB);
    attn_f16_kernel<<<g2, 128, ATTN_SMEM>>>();

    // 3) Output projection (fp16 TC, fp32 output)
    dim3 g3(D_MODEL / 128, NTOK / 128);
    gemm_f16_kernel<false><<<g3, 256, GEMM_SMEM>>>(attnh, wouth, b_out, out, NTOK, D_MODEL, D_MODEL);
}

// round 16
// speedup vs baseline: 1.0786x; 1.0234x over previous
#include <cuda_runtime.h>
#include <cuda_fp16.h>
#include <cstdint>

#define D_MODEL 1024
#define LSEQ    2048
#define NB      2
#define NHEAD   16
#define HD      64
#define NTOK    (NB * LSEQ)   // 4096

// Scratch (device globals — alloc-free per harness rules)
__device__ __half g_qkv[(size_t)NTOK * 3 * D_MODEL];      // [4096, 3072] fp16
__device__ __half g_xh[(size_t)NTOK * D_MODEL];           // x, fp16
__device__ __half g_wqkvh[(size_t)D_MODEL * 3 * D_MODEL]; // W_qkv, fp16
__device__ __half g_wouth[(size_t)D_MODEL * D_MODEL];     // W_out, fp16
__device__ __half g_attnh[(size_t)NTOK * D_MODEL];        // attn out, fp16

// ---------------------------------------------------------------------------
// helpers
// ---------------------------------------------------------------------------
__device__ __forceinline__ void mma_f16(float c[4], const uint32_t a[4], const uint32_t b[2]) {
    asm volatile(
        "mma.sync.aligned.m16n8k16.row.col.f32.f16.f16.f32 "
        "{%0,%1,%2,%3}, {%4,%5,%6,%7}, {%8,%9}, {%0,%1,%2,%3};"
        : "+f"(c[0]), "+f"(c[1]), "+f"(c[2]), "+f"(c[3])
        : "r"(a[0]), "r"(a[1]), "r"(a[2]), "r"(a[3]),
          "r"(b[0]), "r"(b[1]));
}

__device__ __forceinline__ uint32_t pack_half2(float lo, float hi) {
    uint32_t r;
    asm("cvt.rn.f16x2.f32 %0, %1, %2;" : "=r"(r) : "f"(hi), "f"(lo));
    return r;
}

// Two-way fp16 exp2: one MUFU for two P values
__device__ __forceinline__ uint32_t ex2_f16x2(uint32_t x) {
    uint32_t r;
    asm("ex2.approx.f16x2 %0, %1;" : "=r"(r) : "r"(x));
    return r;
}

__device__ __forceinline__ float2 h2_to_f2(uint32_t h2) {
    __half2 h = *reinterpret_cast<__half2*>(&h2);
    return __half22float2(h);
}

__device__ __forceinline__ uint32_t smem_u32(const void* p) {
    return (uint32_t)__cvta_generic_to_shared(p);
}

__device__ __forceinline__ void ldmatrix_x4(uint32_t& r0, uint32_t& r1,
                                            uint32_t& r2, uint32_t& r3, uint32_t addr) {
    asm volatile("ldmatrix.sync.aligned.m8n8.x4.shared.b16 {%0,%1,%2,%3}, [%4];"
                 : "=r"(r0), "=r"(r1), "=r"(r2), "=r"(r3) : "r"(addr));
}
__device__ __forceinline__ void ldmatrix_x4_trans(uint32_t& r0, uint32_t& r1,
                                                  uint32_t& r2, uint32_t& r3, uint32_t addr) {
    asm volatile("ldmatrix.sync.aligned.m8n8.x4.trans.shared.b16 {%0,%1,%2,%3}, [%4];"
                 : "=r"(r0), "=r"(r1), "=r"(r2), "=r"(r3) : "r"(addr));
}

__device__ __forceinline__ void cp_async16(void* smem_dst, const void* gmem_src) {
    uint32_t dst = smem_u32(smem_dst);
    asm volatile("cp.async.cg.shared.global [%0], [%1], 16;" :: "r"(dst), "l"(gmem_src));
}
__device__ __forceinline__ void cp_async_commit() {
    asm volatile("cp.async.commit_group;");
}
template <int N>
__device__ __forceinline__ void cp_async_wait() {
    asm volatile("cp.async.wait_group %0;" :: "n"(N));
}

// ---------------------------------------------------------------------------
// Prep: fp32 -> fp16 (RN)
// ---------------------------------------------------------------------------
__global__ void to_f16_kernel(const float* __restrict__ src,
                              __half* __restrict__ dst, int n4) {
    int i = blockIdx.x * blockDim.x + threadIdx.x;
    if (i < n4) {
        float4 v = reinterpret_cast<const float4*>(src)[i];
        __half2 h0 = __floats2half2_rn(v.x, v.y);
        __half2 h1 = __floats2half2_rn(v.z, v.w);
        reinterpret_cast<__half2*>(dst)[2 * i]     = h0;
        reinterpret_cast<__half2*>(dst)[2 * i + 1] = h1;
    }
}

// ---------------------------------------------------------------------------
// fp16 HMMA GEMM (m16n8k16), BK=64, 3-stage cp.async, ONE sync per k-iter.
// Unchanged from R13 (validated best: QKV 85.5us).
// ---------------------------------------------------------------------------
#define STAGES 3
#define A_STRIDE 72
#define B_STRIDE 136
#define A_STG  (128 * A_STRIDE)
#define B_STG  (64 * B_STRIDE)
#define GEMM_SMEM ((STAGES * (A_STG + B_STG)) * 2)

template <bool HALF_OUT>
__global__ __launch_bounds__(256, 2)
void gemm_f16_kernel(const __half* __restrict__ A,
                     const __half* __restrict__ B,
                     const float* __restrict__ bias,
                     void* __restrict__ Cv,
                     int M, int N, int K) {
    extern __shared__ __align__(16) __half smh[];
    __half* As = smh;
    __half* Bs = smh + STAGES * A_STG;

    const int tid  = threadIdx.x;
    const int w    = tid >> 5;
    const int lane = tid & 31;
    const int gid  = lane >> 2;
    const int tig  = lane & 3;
    const int wm   = w >> 2;
    const int wn   = w & 3;

    const int rowBase = blockIdx.y * 128;
    const int colBase = blockIdx.x * 128;

    const int lrow = lane & 15;
    const int lhi  = (lane >> 4) << 3;

    float acc[4][4][4];
    #pragma unroll
    for (int mt = 0; mt < 4; mt++)
        #pragma unroll
        for (int nt = 0; nt < 4; nt++)
            #pragma unroll
            for (int r = 0; r < 4; r++) acc[mt][nt][r] = 0.0f;

    const int KITERS = K >> 6;

    auto load_slab = [&](int kblk, int sbuf) {
        const int k0 = kblk << 6;
        __half* ad = As + sbuf * A_STG;
        __half* bd = Bs + sbuf * B_STG;
        #pragma unroll
        for (int c = tid; c < 1024; c += 256) {
            int ar = c >> 3, ac = (c & 7) << 3;
            cp_async16(ad + ar * A_STRIDE + ac, &A[(size_t)(rowBase + ar) * K + k0 + ac]);
            int br = c >> 4, bc = (c & 15) << 3;
            cp_async16(bd + br * B_STRIDE + bc, &B[(size_t)(k0 + br) * N + colBase + bc]);
        }
    };

    #pragma unroll
    for (int s = 0; s < STAGES - 1; s++) {
        load_slab(s, s);
        cp_async_commit();
    }

    for (int iter = 0; iter < KITERS; iter++) {
        const int buf = iter % STAGES;
        cp_async_wait<STAGES - 2>();
        __syncthreads();

        const __half* Ab = As + buf * A_STG;
        const __half* Bb = Bs + buf * B_STG;

        #pragma unroll
        for (int kc = 0; kc < 4; kc++) {
            const int kb = kc << 4;
            uint32_t afr[4][4], bfr[4][2];
            #pragma unroll
            for (int mt = 0; mt < 4; mt++) {
                uint32_t addr = smem_u32(&Ab[(wm * 64 + mt * 16 + lrow) * A_STRIDE + kb + lhi]);
                ldmatrix_x4(afr[mt][0], afr[mt][1], afr[mt][2], afr[mt][3], addr);
            }
            #pragma unroll
            for (int ntp = 0; ntp < 2; ntp++) {
                uint32_t addr = smem_u32(&Bb[(kb + lrow) * B_STRIDE + wn * 32 + ntp * 16 + lhi]);
                uint32_t r0, r1, r2, r3;
                ldmatrix_x4_trans(r0, r1, r2, r3, addr);
                bfr[2 * ntp][0] = r0;      bfr[2 * ntp][1] = r1;
                bfr[2 * ntp + 1][0] = r2;  bfr[2 * ntp + 1][1] = r3;
            }
            #pragma unroll
            for (int mt = 0; mt < 4; mt++)
                #pragma unroll
                for (int nt = 0; nt < 4; nt++)
                    mma_f16(acc[mt][nt], afr[mt], bfr[nt]);
        }

        const int kload = iter + STAGES - 1;
        if (kload < KITERS) load_slab(kload, kload % STAGES);
        cp_async_commit();
    }

    #pragma unroll
    for (int mt = 0; mt < 4; mt++) {
        int r0 = rowBase + wm * 64 + mt * 16 + gid;
        #pragma unroll
        for (int nt = 0; nt < 4; nt++) {
            int c0 = colBase + wn * 32 + nt * 8 + 2 * tig;
            float bi0 = bias[c0], bi1 = bias[c0 + 1];
            float s00 = acc[mt][nt][0] + bi0, s01 = acc[mt][nt][1] + bi1;
            float s10 = acc[mt][nt][2] + bi0, s11 = acc[mt][nt][3] + bi1;
            if (HALF_OUT) {
                __half* Ch = (__half*)Cv;
                *reinterpret_cast<uint32_t*>(&Ch[(size_t)r0       * N + c0]) = pack_half2(s00, s01);
                *reinterpret_cast<uint32_t*>(&Ch[(size_t)(r0 + 8) * N + c0]) = pack_half2(s10, s11);
            } else {
                float* Cf = (float*)Cv;
                *reinterpret_cast<float2*>(&Cf[(size_t)r0       * N + c0]) = make_float2(s00, s01);
                *reinterpret_cast<float2*>(&Cf[(size_t)(r0 + 8) * N + c0]) = make_float2(s10, s11);
            }
        }
    }
}

// ---------------------------------------------------------------------------
// fp16 tensor-core flash attention (causal), 64-row Q tiles (R13 structure),
// with 2-way fp16 exp2 softmax: P = ex2.f16x2((s-m)*log2e), halving MUFU
// ops and producing the P-V A-fragments directly. l is summed from the SAME
// fp16 P values (normalization error cancels).
// ---------------------------------------------------------------------------
#define KV_STRIDE 72
#define KV_TILE_H (64 * KV_STRIDE)
#define ATTN_SMEM (4 * KV_TILE_H * 2)
#define LOG2E 1.4426950408889634f

__global__ __launch_bounds__(128, 4)
void attn_f16_kernel() {
    extern __shared__ __align__(16) __half smh[];
    __half* KsB = smh;
    __half* VsB = smh + 2 * KV_TILE_H;

    const int qt = gridDim.x - 1 - blockIdx.x;
    const int h  = blockIdx.y;
    const int b  = blockIdx.z;

    const int tid  = threadIdx.x;
    const int warp = tid >> 5;
    const int lane = tid & 31;
    const int gid  = lane >> 2;
    const int tig  = lane & 3;
    const int lrow = lane & 15;
    const int lhi  = (lane >> 4) << 3;
    const int wrow = warp * 16;
    const int qrow0 = qt * 64;
    const float scale = 0.125f;

    uint32_t qf[4][4];
    {
        const __half* Qb = g_qkv + (size_t)(b * LSEQ + qrow0 + wrow) * 3072 + h * 64;
        #pragma unroll
        for (int kc = 0; kc < 4; kc++) {
            qf[kc][0] = *reinterpret_cast<const uint32_t*>(&Qb[(size_t)gid       * 3072 + kc * 16 + 2 * tig    ]);
            qf[kc][1] = *reinterpret_cast<const uint32_t*>(&Qb[(size_t)(gid + 8) * 3072 + kc * 16 + 2 * tig    ]);
            qf[kc][2] = *reinterpret_cast<const uint32_t*>(&Qb[(size_t)gid       * 3072 + kc * 16 + 2 * tig + 8]);
            qf[kc][3] = *reinterpret_cast<const uint32_t*>(&Qb[(size_t)(gid + 8) * 3072 + kc * 16 + 2 * tig + 8]);
        }
    }

    float o[8][4];
    #pragma unroll
    for (int nt = 0; nt < 8; nt++)
        #pragma unroll
        for (int j = 0; j < 4; j++) o[nt][j] = 0.0f;
    float m0 = -1e30f, m8 = -1e30f, l0 = 0.0f, l8 = 0.0f;

    auto load_tile = [&](int kt, int buf) {
        const __half* base = g_qkv + (size_t)(b * LSEQ + kt * 64) * 3072 + h * 64;
        __half* kd = KsB + buf * KV_TILE_H;
        __half* vd = VsB + buf * KV_TILE_H;
        #pragma unroll
        for (int c = tid; c < 512; c += 128) {
            int r = c >> 3, c8 = (c & 7) << 3;
            const __half* src = base + (size_t)r * 3072 + c8;
            cp_async16(kd + r * KV_STRIDE + c8, src + 1024);
            cp_async16(vd + r * KV_STRIDE + c8, src + 2048);
        }
    };

    load_tile(0, 0);
    cp_async_commit();

    for (int kt = 0; kt <= qt; kt++) {
        const int buf = kt & 1;
        cp_async_wait<0>();
        __syncthreads();

        if (kt < qt) load_tile(kt + 1, buf ^ 1);
        cp_async_commit();

        const __half* Kb = KsB + buf * KV_TILE_H;
        const __half* Vb = VsB + buf * KV_TILE_H;

        // S = Q @ K^T
        float s[8][4];
        #pragma unroll
        for (int nt = 0; nt < 8; nt++)
            #pragma unroll
            for (int j = 0; j < 4; j++) s[nt][j] = 0.0f;

        #pragma unroll
        for (int kc = 0; kc < 4; kc++) {
            #pragma unroll
            for (int ntp = 0; ntp < 4; ntp++) {
                uint32_t addr = smem_u32(&Kb[(ntp * 16 + lrow) * KV_STRIDE + kc * 16 + lhi]);
                uint32_t r0, r1, r2, r3;
                ldmatrix_x4(r0, r1, r2, r3, addr);
                uint32_t b0[2] = {r0, r2};
                uint32_t b1[2] = {r1, r3};
                mma_f16(s[2 * ntp],     qf[kc], b0);
                mma_f16(s[2 * ntp + 1], qf[kc], b1);
            }
        }

        #pragma unroll
        for (int nt = 0; nt < 8; nt++)
            #pragma unroll
            for (int j = 0; j < 4; j++) s[nt][j] *= scale;

        if (kt == qt) {
            const int r0 = wrow + gid, r8 = r0 + 8;
            #pragma unroll
            for (int nt = 0; nt < 8; nt++) {
                int c = nt * 8 + 2 * tig;
                if (c     > r0) s[nt][0] = -1e30f;
                if (c + 1 > r0) s[nt][1] = -1e30f;
                if (c     > r8) s[nt][2] = -1e30f;
                if (c + 1 > r8) s[nt][3] = -1e30f;
            }
        }

        // Row max (fp32, unchanged)
        float mt0 = -1e30f, mt8 = -1e30f;
        #pragma unroll
        for (int nt = 0; nt < 8; nt++) {
            mt0 = fmaxf(mt0, fmaxf(s[nt][0], s[nt][1]));
            mt8 = fmaxf(mt8, fmaxf(s[nt][2], s[nt][3]));
        }
        #pragma unroll
        for (int off = 1; off < 4; off <<= 1) {
            mt0 = fmaxf(mt0, __shfl_xor_sync(0xffffffffu, mt0, off));
            mt8 = fmaxf(mt8, __shfl_xor_sync(0xffffffffu, mt8, off));
        }
        const float mn0 = fmaxf(m0, mt0), mn8 = fmaxf(m8, mt8);
        const float a0 = __expf(m0 - mn0), a8 = __expf(m8 - mn8);
        const float c0 = -mn0 * LOG2E, c8 = -mn8 * LOG2E;

        // P = 2^((s-m)*log2e) via fp16x2 ex2 — p2a/p2b ARE the PV A-fragments
        uint32_t p2a[8], p2b[8];
        float rs0 = 0.0f, rs8 = 0.0f;
        #pragma unroll
        for (int nt = 0; nt < 8; nt++) {
            float t00 = fmaf(s[nt][0], LOG2E, c0);
            float t01 = fmaf(s[nt][1], LOG2E, c0);
            float t80 = fmaf(s[nt][2], LOG2E, c8);
            float t81 = fmaf(s[nt][3], LOG2E, c8);
            p2a[nt] = ex2_f16x2(pack_half2(t00, t01));
            p2b[nt] = ex2_f16x2(pack_half2(t80, t81));
            float2 fa = h2_to_f2(p2a[nt]);
            float2 fb = h2_to_f2(p2b[nt]);
            rs0 += fa.x + fa.y;
            rs8 += fb.x + fb.y;
            o[nt][0] *= a0; o[nt][1] *= a0;
            o[nt][2] *= a8; o[nt][3] *= a8;
        }
        #pragma unroll
        for (int off = 1; off < 4; off <<= 1) {
            rs0 += __shfl_xor_sync(0xffffffffu, rs0, off);
            rs8 += __shfl_xor_sync(0xffffffffu, rs8, off);
        }
        l0 = l0 * a0 + rs0;
        l8 = l8 * a8 + rs8;
        m0 = mn0; m8 = mn8;

        // O += P @ V (A-fragments ready in p2a/p2b)
        #pragma unroll
        for (int kc2 = 0; kc2 < 4; kc2++) {
            uint32_t af[4];
            af[0] = p2a[2 * kc2];
            af[1] = p2b[2 * kc2];
            af[2] = p2a[2 * kc2 + 1];
            af[3] = p2b[2 * kc2 + 1];
            #pragma unroll
            for (int ntp = 0; ntp < 4; ntp++) {
                uint32_t addr = smem_u32(&Vb[(kc2 * 16 + lrow) * KV_STRIDE + ntp * 16 + lhi]);
                uint32_t r0, r1, r2, r3;
                ldmatrix_x4_trans(r0, r1, r2, r3, addr);
                uint32_t b0[2] = {r0, r1};
                uint32_t b1[2] = {r2, r3};
                mma_f16(o[2 * ntp],     af, b0);
                mma_f16(o[2 * ntp + 1], af, b1);
            }
        }
    }

    const float inv0 = 1.0f / l0, inv8 = 1.0f / l8;
    __half* dsth = g_attnh + (size_t)(b * LSEQ + qrow0 + wrow) * D_MODEL + h * 64;
    #pragma unroll
    for (int nt = 0; nt < 8; nt++) {
        int c = nt * 8 + 2 * tig;
        *reinterpret_cast<uint32_t*>(dsth + (size_t)gid       * D_MODEL + c) =
            pack_half2(o[nt][0] * inv0, o[nt][1] * inv0);
        *reinterpret_cast<uint32_t*>(dsth + (size_t)(gid + 8) * D_MODEL + c) =
            pack_half2(o[nt][2] * inv8, o[nt][3] * inv8);
    }
}

// ---------------------------------------------------------------------------
extern "C" void kernel_launch(void* const* d_in, const int* in_sizes, int n_in,
                              void* d_out, int out_size) {
    const float* x     = (const float*)d_in[0];
    const float* W_qkv = (const float*)d_in[1];
    const float* b_qkv = (const float*)d_in[2];
    const float* W_out = (const float*)d_in[3];
    const float* b_out = (const float*)d_in[4];
    float* out = (float*)d_out;

    __half* qkv;   cudaGetSymbolAddress((void**)&qkv,   g_qkv);
    __half* xh;    cudaGetSymbolAddress((void**)&xh,    g_xh);
    __half* wqkvh; cudaGetSymbolAddress((void**)&wqkvh, g_wqkvh);
    __half* wouth; cudaGetSymbolAddress((void**)&wouth, g_wouth);
    __half* attnh; cudaGetSymbolAddress((void**)&attnh, g_attnh);

    cudaFuncSetAttribute(attn_f16_kernel,
                         cudaFuncAttributeMaxDynamicSharedMemorySize, ATTN_SMEM);
    cudaFuncSetAttribute(gemm_f16_kernel<true>,
                         cudaFuncAttributeMaxDynamicSharedMemorySize, GEMM_SMEM);
    cudaFuncSetAttribute(gemm_f16_kernel<false>,
                         cudaFuncAttributeMaxDynamicSharedMemorySize, GEMM_SMEM);

    // 0) Convert inputs to fp16
    {
        int n4x = NTOK * D_MODEL / 4;
        int n4q = D_MODEL * 3 * D_MODEL / 4;
        int n4o = D_MODEL * D_MODEL / 4;
        to_f16_kernel<<<(n4x + 255) / 256, 256>>>(x, xh, n4x);
        to_f16_kernel<<<(n4q + 255) / 256, 256>>>(W_qkv, wqkvh, n4q);
        to_f16_kernel<<<(n4o + 255) / 256, 256>>>(W_out, wouth, n4o);
    }

    // 1) QKV projection (fp16 HMMA, fp16 output)
    dim3 g1(3 * D_MODEL / 128, NTOK / 128);
    gemm_f16_kernel<true><<<g1, 256, GEMM_SMEM>>>(xh, wqkvh, b_qkv, qkv, NTOK, 3 * D_MODEL, D_MODEL);

    // 2) Causal flash attention (fp16 HMMA + fp16x2 exp2 softmax)
    dim3 g2(LSEQ / 64, NHEAD, NB);
    attn_f16_kernel<<<g2, 128, ATTN_SMEM>>>();

    // 3) Output projection (fp16 HMMA, fp32 output)
    dim3 g3(D_MODEL / 128, NTOK / 128);
    gemm_f16_kernel<false><<<g3, 256, GEMM_SMEM>>>(attnh, wouth, b_out, out, NTOK, D_MODEL, D_MODEL);
}

// round 17
// speedup vs baseline: 1.0934x; 1.0138x over previous
#include <cuda_runtime.h>
#include <cuda_fp16.h>
#include <cstdint>

#define D_MODEL 1024
#define LSEQ    2048
#define NB      2
#define NHEAD   16
#define HD      64
#define NTOK    (NB * LSEQ)   // 4096

// Scratch (device globals — alloc-free per harness rules)
__device__ __half g_qkv[(size_t)NTOK * 3 * D_MODEL];      // [4096, 3072] fp16
__device__ __half g_xh[(size_t)NTOK * D_MODEL];           // x, fp16
__device__ __half g_wqkvh[(size_t)D_MODEL * 3 * D_MODEL]; // W_qkv, fp16
__device__ __half g_wouth[(size_t)D_MODEL * D_MODEL];     // W_out, fp16
__device__ __half g_attnh[(size_t)NTOK * D_MODEL];        // attn out, fp16

// ---------------------------------------------------------------------------
// helpers
// ---------------------------------------------------------------------------
__device__ __forceinline__ void mma_f16(float c[4], const uint32_t a[4], const uint32_t b[2]) {
    asm volatile(
        "mma.sync.aligned.m16n8k16.row.col.f32.f16.f16.f32 "
        "{%0,%1,%2,%3}, {%4,%5,%6,%7}, {%8,%9}, {%0,%1,%2,%3};"
        : "+f"(c[0]), "+f"(c[1]), "+f"(c[2]), "+f"(c[3])
        : "r"(a[0]), "r"(a[1]), "r"(a[2]), "r"(a[3]),
          "r"(b[0]), "r"(b[1]));
}

__device__ __forceinline__ uint32_t pack_half2(float lo, float hi) {
    uint32_t r;
    asm("cvt.rn.f16x2.f32 %0, %1, %2;" : "=r"(r) : "f"(hi), "f"(lo));
    return r;
}

// Two-way fp16 exp2: one MUFU for two P values
__device__ __forceinline__ uint32_t ex2_f16x2(uint32_t x) {
    uint32_t r;
    asm("ex2.approx.f16x2 %0, %1;" : "=r"(r) : "r"(x));
    return r;
}

__device__ __forceinline__ float2 h2_to_f2(uint32_t h2) {
    __half2 h = *reinterpret_cast<__half2*>(&h2);
    return __half22float2(h);
}

__device__ __forceinline__ uint32_t smem_u32(const void* p) {
    return (uint32_t)__cvta_generic_to_shared(p);
}

__device__ __forceinline__ void ldmatrix_x4(uint32_t& r0, uint32_t& r1,
                                            uint32_t& r2, uint32_t& r3, uint32_t addr) {
    asm volatile("ldmatrix.sync.aligned.m8n8.x4.shared.b16 {%0,%1,%2,%3}, [%4];"
                 : "=r"(r0), "=r"(r1), "=r"(r2), "=r"(r3) : "r"(addr));
}
__device__ __forceinline__ void ldmatrix_x4_trans(uint32_t& r0, uint32_t& r1,
                                                  uint32_t& r2, uint32_t& r3, uint32_t addr) {
    asm volatile("ldmatrix.sync.aligned.m8n8.x4.trans.shared.b16 {%0,%1,%2,%3}, [%4];"
                 : "=r"(r0), "=r"(r1), "=r"(r2), "=r"(r3) : "r"(addr));
}

__device__ __forceinline__ void cp_async16(void* smem_dst, const void* gmem_src) {
    uint32_t dst = smem_u32(smem_dst);
    asm volatile("cp.async.cg.shared.global [%0], [%1], 16;" :: "r"(dst), "l"(gmem_src));
}
__device__ __forceinline__ void cp_async_commit() {
    asm volatile("cp.async.commit_group;");
}
template <int N>
__device__ __forceinline__ void cp_async_wait() {
    asm volatile("cp.async.wait_group %0;" :: "n"(N));
}

// ---------------------------------------------------------------------------
// Prep: fp32 -> fp16 (RN)
// ---------------------------------------------------------------------------
__global__ void to_f16_kernel(const float* __restrict__ src,
                              __half* __restrict__ dst, int n4) {
    int i = blockIdx.x * blockDim.x + threadIdx.x;
    if (i < n4) {
        float4 v = reinterpret_cast<const float4*>(src)[i];
        __half2 h0 = __floats2half2_rn(v.x, v.y);
        __half2 h1 = __floats2half2_rn(v.z, v.w);
        reinterpret_cast<__half2*>(dst)[2 * i]     = h0;
        reinterpret_cast<__half2*>(dst)[2 * i + 1] = h1;
    }
}

// ---------------------------------------------------------------------------
// fp16 HMMA GEMM (m16n8k16), BK=64, 3-stage cp.async, ONE sync per k-iter.
// Unchanged (validated: QKV 85.3us).
// ---------------------------------------------------------------------------
#define STAGES 3
#define A_STRIDE 72
#define B_STRIDE 136
#define A_STG  (128 * A_STRIDE)
#define B_STG  (64 * B_STRIDE)
#define GEMM_SMEM ((STAGES * (A_STG + B_STG)) * 2)

template <bool HALF_OUT>
__global__ __launch_bounds__(256, 2)
void gemm_f16_kernel(const __half* __restrict__ A,
                     const __half* __restrict__ B,
                     const float* __restrict__ bias,
                     void* __restrict__ Cv,
                     int M, int N, int K) {
    extern __shared__ __align__(16) __half smh[];
    __half* As = smh;
    __half* Bs = smh + STAGES * A_STG;

    const int tid  = threadIdx.x;
    const int w    = tid >> 5;
    const int lane = tid & 31;
    const int gid  = lane >> 2;
    const int tig  = lane & 3;
    const int wm   = w >> 2;
    const int wn   = w & 3;

    const int rowBase = blockIdx.y * 128;
    const int colBase = blockIdx.x * 128;

    const int lrow = lane & 15;
    const int lhi  = (lane >> 4) << 3;

    float acc[4][4][4];
    #pragma unroll
    for (int mt = 0; mt < 4; mt++)
        #pragma unroll
        for (int nt = 0; nt < 4; nt++)
            #pragma unroll
            for (int r = 0; r < 4; r++) acc[mt][nt][r] = 0.0f;

    const int KITERS = K >> 6;

    auto load_slab = [&](int kblk, int sbuf) {
        const int k0 = kblk << 6;
        __half* ad = As + sbuf * A_STG;
        __half* bd = Bs + sbuf * B_STG;
        #pragma unroll
        for (int c = tid; c < 1024; c += 256) {
            int ar = c >> 3, ac = (c & 7) << 3;
            cp_async16(ad + ar * A_STRIDE + ac, &A[(size_t)(rowBase + ar) * K + k0 + ac]);
            int br = c >> 4, bc = (c & 15) << 3;
            cp_async16(bd + br * B_STRIDE + bc, &B[(size_t)(k0 + br) * N + colBase + bc]);
        }
    };

    #pragma unroll
    for (int s = 0; s < STAGES - 1; s++) {
        load_slab(s, s);
        cp_async_commit();
    }

    for (int iter = 0; iter < KITERS; iter++) {
        const int buf = iter % STAGES;
        cp_async_wait<STAGES - 2>();
        __syncthreads();

        const __half* Ab = As + buf * A_STG;
        const __half* Bb = Bs + buf * B_STG;

        #pragma unroll
        for (int kc = 0; kc < 4; kc++) {
            const int kb = kc << 4;
            uint32_t afr[4][4], bfr[4][2];
            #pragma unroll
            for (int mt = 0; mt < 4; mt++) {
                uint32_t addr = smem_u32(&Ab[(wm * 64 + mt * 16 + lrow) * A_STRIDE + kb + lhi]);
                ldmatrix_x4(afr[mt][0], afr[mt][1], afr[mt][2], afr[mt][3], addr);
            }
            #pragma unroll
            for (int ntp = 0; ntp < 2; ntp++) {
                uint32_t addr = smem_u32(&Bb[(kb + lrow) * B_STRIDE + wn * 32 + ntp * 16 + lhi]);
                uint32_t r0, r1, r2, r3;
                ldmatrix_x4_trans(r0, r1, r2, r3, addr);
                bfr[2 * ntp][0] = r0;      bfr[2 * ntp][1] = r1;
                bfr[2 * ntp + 1][0] = r2;  bfr[2 * ntp + 1][1] = r3;
            }
            #pragma unroll
            for (int mt = 0; mt < 4; mt++)
                #pragma unroll
                for (int nt = 0; nt < 4; nt++)
                    mma_f16(acc[mt][nt], afr[mt], bfr[nt]);
        }

        const int kload = iter + STAGES - 1;
        if (kload < KITERS) load_slab(kload, kload % STAGES);
        cp_async_commit();
    }

    #pragma unroll
    for (int mt = 0; mt < 4; mt++) {
        int r0 = rowBase + wm * 64 + mt * 16 + gid;
        #pragma unroll
        for (int nt = 0; nt < 4; nt++) {
            int c0 = colBase + wn * 32 + nt * 8 + 2 * tig;
            float bi0 = bias[c0], bi1 = bias[c0 + 1];
            float s00 = acc[mt][nt][0] + bi0, s01 = acc[mt][nt][1] + bi1;
            float s10 = acc[mt][nt][2] + bi0, s11 = acc[mt][nt][3] + bi1;
            if (HALF_OUT) {
                __half* Ch = (__half*)Cv;
                *reinterpret_cast<uint32_t*>(&Ch[(size_t)r0       * N + c0]) = pack_half2(s00, s01);
                *reinterpret_cast<uint32_t*>(&Ch[(size_t)(r0 + 8) * N + c0]) = pack_half2(s10, s11);
            } else {
                float* Cf = (float*)Cv;
                *reinterpret_cast<float2*>(&Cf[(size_t)r0       * N + c0]) = make_float2(s00, s01);
                *reinterpret_cast<float2*>(&Cf[(size_t)(r0 + 8) * N + c0]) = make_float2(s10, s11);
            }
        }
    }
}

// ---------------------------------------------------------------------------
// fp16 tensor-core flash attention (causal), 64-row Q tiles, fp16x2 exp2
// softmax (R15) + SCALE FOLDING (this round): the explicit s*=scale pass
// (32 FMUL/warp/tile) is absorbed into the row-max (mt*scale, 2 FMUL) and
// the exp FMAF (s*(scale*log2e) + c). Mask/max operate on raw scores.
// ---------------------------------------------------------------------------
#define KV_STRIDE 72
#define KV_TILE_H (64 * KV_STRIDE)
#define ATTN_SMEM (4 * KV_TILE_H * 2)
#define LOG2E 1.4426950408889634f
#define SCALE 0.125f

__global__ __launch_bounds__(128, 4)
void attn_f16_kernel() {
    extern __shared__ __align__(16) __half smh[];
    __half* KsB = smh;
    __half* VsB = smh + 2 * KV_TILE_H;

    const int qt = gridDim.x - 1 - blockIdx.x;
    const int h  = blockIdx.y;
    const int b  = blockIdx.z;

    const int tid  = threadIdx.x;
    const int warp = tid >> 5;
    const int lane = tid & 31;
    const int gid  = lane >> 2;
    const int tig  = lane & 3;
    const int lrow = lane & 15;
    const int lhi  = (lane >> 4) << 3;
    const int wrow = warp * 16;
    const int qrow0 = qt * 64;
    const float kfac = SCALE * LOG2E;   // exp absorbs scale

    uint32_t qf[4][4];
    {
        const __half* Qb = g_qkv + (size_t)(b * LSEQ + qrow0 + wrow) * 3072 + h * 64;
        #pragma unroll
        for (int kc = 0; kc < 4; kc++) {
            qf[kc][0] = *reinterpret_cast<const uint32_t*>(&Qb[(size_t)gid       * 3072 + kc * 16 + 2 * tig    ]);
            qf[kc][1] = *reinterpret_cast<const uint32_t*>(&Qb[(size_t)(gid + 8) * 3072 + kc * 16 + 2 * tig    ]);
            qf[kc][2] = *reinterpret_cast<const uint32_t*>(&Qb[(size_t)gid       * 3072 + kc * 16 + 2 * tig + 8]);
            qf[kc][3] = *reinterpret_cast<const uint32_t*>(&Qb[(size_t)(gid + 8) * 3072 + kc * 16 + 2 * tig + 8]);
        }
    }

    float o[8][4];
    #pragma unroll
    for (int nt = 0; nt < 8; nt++)
        #pragma unroll
        for (int j = 0; j < 4; j++) o[nt][j] = 0.0f;
    // m tracked in SCALED units
    float m0 = -1e30f, m8 = -1e30f, l0 = 0.0f, l8 = 0.0f;

    auto load_tile = [&](int kt, int buf) {
        const __half* base = g_qkv + (size_t)(b * LSEQ + kt * 64) * 3072 + h * 64;
        __half* kd = KsB + buf * KV_TILE_H;
        __half* vd = VsB + buf * KV_TILE_H;
        #pragma unroll
        for (int c = tid; c < 512; c += 128) {
            int r = c >> 3, c8 = (c & 7) << 3;
            const __half* src = base + (size_t)r * 3072 + c8;
            cp_async16(kd + r * KV_STRIDE + c8, src + 1024);
            cp_async16(vd + r * KV_STRIDE + c8, src + 2048);
        }
    };

    load_tile(0, 0);
    cp_async_commit();

    for (int kt = 0; kt <= qt; kt++) {
        const int buf = kt & 1;
        cp_async_wait<0>();
        __syncthreads();

        if (kt < qt) load_tile(kt + 1, buf ^ 1);
        cp_async_commit();

        const __half* Kb = KsB + buf * KV_TILE_H;
        const __half* Vb = VsB + buf * KV_TILE_H;

        // S = Q @ K^T (raw, unscaled)
        float s[8][4];
        #pragma unroll
        for (int nt = 0; nt < 8; nt++)
            #pragma unroll
            for (int j = 0; j < 4; j++) s[nt][j] = 0.0f;

        #pragma unroll
        for (int kc = 0; kc < 4; kc++) {
            #pragma unroll
            for (int ntp = 0; ntp < 4; ntp++) {
                uint32_t addr = smem_u32(&Kb[(ntp * 16 + lrow) * KV_STRIDE + kc * 16 + lhi]);
                uint32_t r0, r1, r2, r3;
                ldmatrix_x4(r0, r1, r2, r3, addr);
                uint32_t b0[2] = {r0, r2};
                uint32_t b1[2] = {r1, r3};
                mma_f16(s[2 * ntp],     qf[kc], b0);
                mma_f16(s[2 * ntp + 1], qf[kc], b1);
            }
        }

        // Causal mask on raw scores
        if (kt == qt) {
            const int r0 = wrow + gid, r8 = r0 + 8;
            #pragma unroll
            for (int nt = 0; nt < 8; nt++) {
                int c = nt * 8 + 2 * tig;
                if (c     > r0) s[nt][0] = -1e30f;
                if (c + 1 > r0) s[nt][1] = -1e30f;
                if (c     > r8) s[nt][2] = -1e30f;
                if (c + 1 > r8) s[nt][3] = -1e30f;
            }
        }

        // Row max over RAW s; scale applied once per row pair
        float mt0 = -1e30f, mt8 = -1e30f;
        #pragma unroll
        for (int nt = 0; nt < 8; nt++) {
            mt0 = fmaxf(mt0, fmaxf(s[nt][0], s[nt][1]));
            mt8 = fmaxf(mt8, fmaxf(s[nt][2], s[nt][3]));
        }
        #pragma unroll
        for (int off = 1; off < 4; off <<= 1) {
            mt0 = fmaxf(mt0, __shfl_xor_sync(0xffffffffu, mt0, off));
            mt8 = fmaxf(mt8, __shfl_xor_sync(0xffffffffu, mt8, off));
        }
        const float mn0 = fmaxf(m0, mt0 * SCALE), mn8 = fmaxf(m8, mt8 * SCALE);
        const float a0 = __expf(m0 - mn0), a8 = __expf(m8 - mn8);
        const float c0 = -mn0 * LOG2E, c8 = -mn8 * LOG2E;

        // P = 2^(s*kfac + c) via fp16x2 ex2 — p2a/p2b ARE the PV A-fragments
        uint32_t p2a[8], p2b[8];
        float rs0 = 0.0f, rs8 = 0.0f;
        #pragma unroll
        for (int nt = 0; nt < 8; nt++) {
            float t00 = fmaf(s[nt][0], kfac, c0);
            float t01 = fmaf(s[nt][1], kfac, c0);
            float t80 = fmaf(s[nt][2], kfac, c8);
            float t81 = fmaf(s[nt][3], kfac, c8);
            p2a[nt] = ex2_f16x2(pack_half2(t00, t01));
            p2b[nt] = ex2_f16x2(pack_half2(t80, t81));
            float2 fa = h2_to_f2(p2a[nt]);
            float2 fb = h2_to_f2(p2b[nt]);
            rs0 += fa.x + fa.y;
            rs8 += fb.x + fb.y;
            o[nt][0] *= a0; o[nt][1] *= a0;
            o[nt][2] *= a8; o[nt][3] *= a8;
        }
        #pragma unroll
        for (int off = 1; off < 4; off <<= 1) {
            rs0 += __shfl_xor_sync(0xffffffffu, rs0, off);
            rs8 += __shfl_xor_sync(0xffffffffu, rs8, off);
        }
        l0 = l0 * a0 + rs0;
        l8 = l8 * a8 + rs8;
        m0 = mn0; m8 = mn8;

        // O += P @ V
        #pragma unroll
        for (int kc2 = 0; kc2 < 4; kc2++) {
            uint32_t af[4];
            af[0] = p2a[2 * kc2];
            af[1] = p2b[2 * kc2];
            af[2] = p2a[2 * kc2 + 1];
            af[3] = p2b[2 * kc2 + 1];
            #pragma unroll
            for (int ntp = 0; ntp < 4; ntp++) {
                uint32_t addr = smem_u32(&Vb[(kc2 * 16 + lrow) * KV_STRIDE + ntp * 16 + lhi]);
                uint32_t r0, r1, r2, r3;
                ldmatrix_x4_trans(r0, r1, r2, r3, addr);
                uint32_t b0[2] = {r0, r1};
                uint32_t b1[2] = {r2, r3};
                mma_f16(o[2 * ntp],     af, b0);
                mma_f16(o[2 * ntp + 1], af, b1);
            }
        }
    }

    const float inv0 = 1.0f / l0, inv8 = 1.0f / l8;
    __half* dsth = g_attnh + (size_t)(b * LSEQ + qrow0 + wrow) * D_MODEL + h * 64;
    #pragma unroll
    for (int nt = 0; nt < 8; nt++) {
        int c = nt * 8 + 2 * tig;
        *reinterpret_cast<uint32_t*>(dsth + (size_t)gid       * D_MODEL + c) =
            pack_half2(o[nt][0] * inv0, o[nt][1] * inv0);
        *reinterpret_cast<uint32_t*>(dsth + (size_t)(gid + 8) * D_MODEL + c) =
            pack_half2(o[nt][2] * inv8, o[nt][3] * inv8);
    }
}

// ---------------------------------------------------------------------------
extern "C" void kernel_launch(void* const* d_in, const int* in_sizes, int n_in,
                              void* d_out, int out_size) {
    const float* x     = (const float*)d_in[0];
    const float* W_qkv = (const float*)d_in[1];
    const float* b_qkv = (const float*)d_in[2];
    const float* W_out = (const float*)d_in[3];
    const float* b_out = (const float*)d_in[4];
    float* out = (float*)d_out;

    __half* qkv;   cudaGetSymbolAddress((void**)&qkv,   g_qkv);
    __half* xh;    cudaGetSymbolAddress((void**)&xh,    g_xh);
    __half* wqkvh; cudaGetSymbolAddress((void**)&wqkvh, g_wqkvh);
    __half* wouth; cudaGetSymbolAddress((void**)&wouth, g_wouth);
    __half* attnh; cudaGetSymbolAddress((void**)&attnh, g_attnh);

    cudaFuncSetAttribute(attn_f16_kernel,
                         cudaFuncAttributeMaxDynamicSharedMemorySize, ATTN_SMEM);
    cudaFuncSetAttribute(gemm_f16_kernel<true>,
                         cudaFuncAttributeMaxDynamicSharedMemorySize, GEMM_SMEM);
    cudaFuncSetAttribute(gemm_f16_kernel<false>,
                         cudaFuncAttributeMaxDynamicSharedMemorySize, GEMM_SMEM);

    // 0) Convert inputs to fp16
    {
        int n4x = NTOK * D_MODEL / 4;
        int n4q = D_MODEL * 3 * D_MODEL / 4;
        int n4o = D_MODEL * D_MODEL / 4;
        to_f16_kernel<<<(n4x + 255) / 256, 256>>>(x, xh, n4x);
        to_f16_kernel<<<(n4q + 255) / 256, 256>>>(W_qkv, wqkvh, n4q);
        to_f16_kernel<<<(n4o + 255) / 256, 256>>>(W_out, wouth, n4o);
    }

    // 1) QKV projection (fp16 HMMA, fp16 output)
    dim3 g1(3 * D_MODEL / 128, NTOK / 128);
    gemm_f16_kernel<true><<<g1, 256, GEMM_SMEM>>>(xh, wqkvh, b_qkv, qkv, NTOK, 3 * D_MODEL, D_MODEL);

    // 2) Causal flash attention (fp16 HMMA, scale-folded fp16x2 softmax)
    dim3 g2(LSEQ / 64, NHEAD, NB);
    attn_f16_kernel<<<g2, 128, ATTN_SMEM>>>();

    // 3) Output projection (fp16 HMMA, fp32 output)
    dim3 g3(D_MODEL / 128, NTOK / 128);
    gemm_f16_kernel<false><<<g3, 256, GEMM_SMEM>>>(attnh, wouth, b_out, out, NTOK, D_MODEL, D_MODEL);
}